// round 9
// baseline (speedup 1.0000x reference)
#include <cuda_runtime.h>
#include <math.h>

#define NN 100000
#define EE 1600000
#define CC 32
#define SCAN_T 512
#define NB ((NN + SCAN_T - 1) / SCAN_T)   /* 196 */

// ---------------- scratch (static device globals; no allocation) -------------
__device__ float g_deg[NN];
__device__ __align__(8) int g_zbuf[NN + 512];   // cnt + scan state
__device__ int   g_row[NN + 1];
__device__ int   g_cur[NN];
__device__ int2  g_csr[EE];          // (src, coef bits), grouped by dst
__device__ float g_aggx[NN * CC];    // phase1: agg(x);  reused in phase2 as agg(hr)
__device__ float g_aggh[NN * CC];    // agg(h)
__device__ float g_px2[NN * CC];     // gate-2 x-side preactivation (incl. bias)
__device__ float g_z[NN * CC];
__device__ float g_hr[NN * CC];

// ---------------- f32x2 packed-FMA helpers -----------------------------------
__device__ __forceinline__ unsigned long long pack2(float a, float b) {
    unsigned long long v;
    asm("mov.b64 %0, {%1, %2};" : "=l"(v) : "f"(a), "f"(b));
    return v;
}
__device__ __forceinline__ float2 unpack2(unsigned long long v) {
    float2 r;
    asm("mov.b64 {%0, %1}, %2;" : "=f"(r.x), "=f"(r.y) : "l"(v));
    return r;
}
__device__ __forceinline__ void fma2(unsigned long long& acc, float w0, float w1,
                                     float s0, float s1) {
    unsigned long long wv = pack2(w0, w1);
    unsigned long long sv = pack2(s0, s1);
    asm("fma.rn.f32x2 %0, %1, %2, %3;" : "=l"(acc) : "l"(wv), "l"(sv), "l"(acc));
}

// ---------------- k_deg_hist: 4 edges per thread ------------------------------
__global__ void k_deg_hist(const int* __restrict__ ei, const float* __restrict__ w) {
    int t = blockIdx.x * blockDim.x + threadIdx.x;
    if (t >= EE / 4) return;
    int4 s = ((const int4*)ei)[t];
    int4 d = ((const int4*)(ei + EE))[t];
    float4 wv = ((const float4*)w)[t];
    atomicAdd(&g_deg[s.x], wv.x);
    atomicAdd(&g_deg[s.y], wv.y);
    atomicAdd(&g_deg[s.z], wv.z);
    atomicAdd(&g_deg[s.w], wv.w);
    atomicAdd(&g_zbuf[d.x], 1);
    atomicAdd(&g_zbuf[d.y], 1);
    atomicAdd(&g_zbuf[d.z], 1);
    atomicAdd(&g_zbuf[d.w], 1);
}

// ---------------- k_scan: single-pass exclusive scan, warp-parallel lookback --
__global__ void k_scan() {
    __shared__ int s[SCAN_T];
    __shared__ int sPrefix;
    unsigned long long* state = (unsigned long long*)(g_zbuf + NN);
    int t = threadIdx.x;
    int b = blockIdx.x;
    int i = b * SCAN_T + t;
    int v = (i < NN) ? g_zbuf[i] : 0;
    s[t] = v;
    __syncthreads();
    for (int off = 1; off < SCAN_T; off <<= 1) {
        int a = (t >= off) ? s[t - off] : 0;
        __syncthreads();
        s[t] += a;
        __syncthreads();
    }
    int total = s[SCAN_T - 1];

    if (b == 0) {
        if (t == 0) { atomicExch(&state[0], (2ULL << 32) | (unsigned)total); sPrefix = 0; }
    } else if (t < 32) {
        if (t == 0) atomicExch(&state[b], (1ULL << 32) | (unsigned)total);
        int prefix = 0;
        int j = b - 1 - t;
        for (;;) {
            unsigned flag = 0; int val = 0;
            if (j >= 0) {
                unsigned long long sj;
                do { sj = atomicOr(&state[j], 0ULL); flag = (unsigned)(sj >> 32); }
                while (flag == 0u);
                val = (int)(unsigned)sj;
            }
            unsigned incmask = __ballot_sync(0xffffffffu, (j >= 0) && flag == 2u);
            if (incmask) {
                int k = __ffs(incmask) - 1;
                if (t > k) val = 0;
            }
#pragma unroll
            for (int off = 16; off > 0; off >>= 1)
                val += __shfl_xor_sync(0xffffffffu, val, off);
            prefix += val;
            if (incmask) break;
            j -= 32;
        }
        if (t == 0) {
            atomicExch(&state[b], (2ULL << 32) | (unsigned)(prefix + total));
            sPrefix = prefix;
        }
    }
    __syncthreads();
    int pre = (b == 0) ? 0 : sPrefix;
    if (i < NN) {
        int rs = pre + s[t] - v;
        g_row[i] = rs;
        g_cur[i] = rs;
    }
    if (b == 0 && t == 0) g_row[NN] = EE;
}

// ---------------- k_place: 4 edges per thread ---------------------------------
__global__ void k_place(const int* __restrict__ ei, const float* __restrict__ w) {
    int t = blockIdx.x * blockDim.x + threadIdx.x;
    if (t >= EE / 4) return;
    int4 s = ((const int4*)ei)[t];
    int4 d = ((const int4*)(ei + EE))[t];
    float4 wv = ((const float4*)w)[t];
    float ds0 = g_deg[s.x], ds1 = g_deg[s.y], ds2 = g_deg[s.z], ds3 = g_deg[s.w];
    float dd0 = g_deg[d.x], dd1 = g_deg[d.y], dd2 = g_deg[d.z], dd3 = g_deg[d.w];
    float c0 = -((ds0 > 0.f ? rsqrtf(ds0) : 0.f) * wv.x * (dd0 > 0.f ? rsqrtf(dd0) : 0.f));
    float c1 = -((ds1 > 0.f ? rsqrtf(ds1) : 0.f) * wv.y * (dd1 > 0.f ? rsqrtf(dd1) : 0.f));
    float c2 = -((ds2 > 0.f ? rsqrtf(ds2) : 0.f) * wv.z * (dd2 > 0.f ? rsqrtf(dd2) : 0.f));
    float c3 = -((ds3 > 0.f ? rsqrtf(ds3) : 0.f) * wv.w * (dd3 > 0.f ? rsqrtf(dd3) : 0.f));
    int p0 = atomicAdd(&g_cur[d.x], 1);
    int p1 = atomicAdd(&g_cur[d.y], 1);
    int p2 = atomicAdd(&g_cur[d.z], 1);
    int p3 = atomicAdd(&g_cur[d.w], 1);
    g_csr[p0] = make_int2(s.x, __float_as_int(c0));
    g_csr[p1] = make_int2(s.y, __float_as_int(c1));
    g_csr[p2] = make_int2(s.z, __float_as_int(c2));
    g_csr[p3] = make_int2(s.w, __float_as_int(c3));
}

// ---------------- gathers (unroll 8 for MLP) -----------------------------------
__device__ __forceinline__ void gather2(int node, int lane,
                                        const float* __restrict__ a,
                                        const float* __restrict__ b,
                                        float& ra, float& rb) {
    int beg = g_row[node], end = g_row[node + 1];
    float sa = 0.0f, sb = 0.0f;
    int e = beg;
    for (; e + 8 <= end; e += 8) {
        int2 t0 = g_csr[e],     t1 = g_csr[e + 1], t2 = g_csr[e + 2], t3 = g_csr[e + 3];
        int2 t4 = g_csr[e + 4], t5 = g_csr[e + 5], t6 = g_csr[e + 6], t7 = g_csr[e + 7];
        float a0 = a[t0.x * CC + lane], a1 = a[t1.x * CC + lane];
        float a2 = a[t2.x * CC + lane], a3 = a[t3.x * CC + lane];
        float a4 = a[t4.x * CC + lane], a5 = a[t5.x * CC + lane];
        float a6 = a[t6.x * CC + lane], a7 = a[t7.x * CC + lane];
        float b0 = b[t0.x * CC + lane], b1 = b[t1.x * CC + lane];
        float b2 = b[t2.x * CC + lane], b3 = b[t3.x * CC + lane];
        float b4 = b[t4.x * CC + lane], b5 = b[t5.x * CC + lane];
        float b6 = b[t6.x * CC + lane], b7 = b[t7.x * CC + lane];
        sa += __int_as_float(t0.y) * a0 + __int_as_float(t1.y) * a1
            + __int_as_float(t2.y) * a2 + __int_as_float(t3.y) * a3
            + __int_as_float(t4.y) * a4 + __int_as_float(t5.y) * a5
            + __int_as_float(t6.y) * a6 + __int_as_float(t7.y) * a7;
        sb += __int_as_float(t0.y) * b0 + __int_as_float(t1.y) * b1
            + __int_as_float(t2.y) * b2 + __int_as_float(t3.y) * b3
            + __int_as_float(t4.y) * b4 + __int_as_float(t5.y) * b5
            + __int_as_float(t6.y) * b6 + __int_as_float(t7.y) * b7;
    }
    for (; e < end; e++) {
        int2 t = g_csr[e];
        float c = __int_as_float(t.y);
        sa += c * a[t.x * CC + lane];
        sb += c * b[t.x * CC + lane];
    }
    ra = sa; rb = sb;
}

__device__ __forceinline__ void gather1(int node, int lane,
                                        const float* __restrict__ a, float& ra) {
    int beg = g_row[node], end = g_row[node + 1];
    float sa = 0.0f;
    int e = beg;
    for (; e + 8 <= end; e += 8) {
        int2 t0 = g_csr[e],     t1 = g_csr[e + 1], t2 = g_csr[e + 2], t3 = g_csr[e + 3];
        int2 t4 = g_csr[e + 4], t5 = g_csr[e + 5], t6 = g_csr[e + 6], t7 = g_csr[e + 7];
        float a0 = a[t0.x * CC + lane], a1 = a[t1.x * CC + lane];
        float a2 = a[t2.x * CC + lane], a3 = a[t3.x * CC + lane];
        float a4 = a[t4.x * CC + lane], a5 = a[t5.x * CC + lane];
        float a6 = a[t6.x * CC + lane], a7 = a[t7.x * CC + lane];
        sa += __int_as_float(t0.y) * a0 + __int_as_float(t1.y) * a1
            + __int_as_float(t2.y) * a2 + __int_as_float(t3.y) * a3
            + __int_as_float(t4.y) * a4 + __int_as_float(t5.y) * a5
            + __int_as_float(t6.y) * a6 + __int_as_float(t7.y) * a7;
    }
    for (; e < end; e++) {
        int2 t = g_csr[e];
        sa += __int_as_float(t.y) * a[t.x * CC + lane];
    }
    ra = sa;
}

// ---------------- k_gather_xh: warp-per-node, zero smem, max occupancy --------
__global__ void __launch_bounds__(256) k_gather_xh(
        const float* __restrict__ x, const float* __restrict__ h) {
    int lane = threadIdx.x & 31;
    int node = (blockIdx.x * blockDim.x + threadIdx.x) >> 5;
    if (node >= NN) return;
    float ax, ah;
    gather2(node, lane, x, h, ax, ah);
    int base = node * CC + lane;
    g_aggx[base] = ax;
    g_aggh[base] = ah;
}

// ---------------- k_gather_hr: warp-per-node gather of hr ---------------------
// output goes into g_aggx (dead after k_gates)
__global__ void __launch_bounds__(256) k_gather_hr() {
    int lane = threadIdx.x & 31;
    int node = (blockIdx.x * blockDim.x + threadIdx.x) >> 5;
    if (node >= NN) return;
    float ahr;
    gather1(node, lane, g_hr, ahr);
    g_aggx[node * CC + lane] = ahr;
}

// ---------------- k_gates: PURE compute: gates z,r + px2 (4 nodes/warp) -------
__global__ void __launch_bounds__(256) k_gates(
        const float* __restrict__ x, const float* __restrict__ h,
        const float* __restrict__ Wx, const float* __restrict__ bx,
        const float* __restrict__ Wh, const float* __restrict__ bh) {
    extern __shared__ float4 dynw[];
    float4* sZ0 = dynw;            // z: Wx[0,0] k-quads
    float4* sZ1 = dynw + 256;      // z: Wx[0,1]
    float4* sZ2 = dynw + 512;      // z: Wh[0,0]
    float4* sZ3 = dynw + 768;      // z: Wh[0,1]
    float4* sR0 = dynw + 1024;     // r: Wx[1,0]
    float4* sR1 = dynw + 1280;     // r: Wx[1,1]
    float4* sR2 = dynw + 1536;     // r: Wh[1,0]
    float4* sR3 = dynw + 1792;     // r: Wh[1,1]
    float4* sP0 = dynw + 2048;     // px2: Wx[2,0]
    float4* sP1 = dynw + 2304;     // px2: Wx[2,1]
    __shared__ __align__(16) float sIn[8 * 4 * 4 * 32];  // 16KB

    int tid = threadIdx.x;
    for (int i = tid; i < 256; i += blockDim.x) {
        int q = i >> 5, c = i & 31;
        int o = q * 128 + c;
        sZ0[i] = make_float4(Wx[o],        Wx[o + 32],        Wx[o + 64],        Wx[o + 96]);
        sZ1[i] = make_float4(Wx[1024 + o], Wx[1024 + o + 32], Wx[1024 + o + 64], Wx[1024 + o + 96]);
        sZ2[i] = make_float4(Wh[o],        Wh[o + 32],        Wh[o + 64],        Wh[o + 96]);
        sZ3[i] = make_float4(Wh[1024 + o], Wh[1024 + o + 32], Wh[1024 + o + 64], Wh[1024 + o + 96]);
        sR0[i] = make_float4(Wx[2048 + o], Wx[2048 + o + 32], Wx[2048 + o + 64], Wx[2048 + o + 96]);
        sR1[i] = make_float4(Wx[3072 + o], Wx[3072 + o + 32], Wx[3072 + o + 64], Wx[3072 + o + 96]);
        sR2[i] = make_float4(Wh[2048 + o], Wh[2048 + o + 32], Wh[2048 + o + 64], Wh[2048 + o + 96]);
        sR3[i] = make_float4(Wh[3072 + o], Wh[3072 + o + 32], Wh[3072 + o + 64], Wh[3072 + o + 96]);
        sP0[i] = make_float4(Wx[4096 + o], Wx[4096 + o + 32], Wx[4096 + o + 64], Wx[4096 + o + 96]);
        sP1[i] = make_float4(Wx[5120 + o], Wx[5120 + o + 32], Wx[5120 + o + 64], Wx[5120 + o + 96]);
    }
    __syncthreads();

    int lane = tid & 31;
    int warp = tid >> 5;
    float bz = bx[lane] + bh[lane];
    float br = bx[32 + lane] + bh[32 + lane];
    float b2 = bx[64 + lane] + bh[64 + lane];

    int gw = blockIdx.x * 8 + warp;
    int stride = gridDim.x * 8 * 4;
    float* stage = &sIn[warp * 512];

    for (int nb = gw * 4; nb < NN; nb += stride) {
        float hv[4];
#pragma unroll
        for (int i = 0; i < 4; i++) {
            int node = nb + i;
            float xv = 0.f, hvv = 0.f, ax = 0.f, ah = 0.f;
            if (node < NN) {
                int base = node * CC + lane;
                xv = x[base];
                hvv = h[base];
                ax = g_aggx[base];
                ah = g_aggh[base];
            }
            hv[i] = hvv;
            stage[i * 128 +  0 + lane] = xv;
            stage[i * 128 + 32 + lane] = ax;
            stage[i * 128 + 64 + lane] = hvv;
            stage[i * 128 + 96 + lane] = ah;
        }
        __syncwarp();

        unsigned long long accz[4], accr[4], accp[4];
#pragma unroll
        for (int i = 0; i < 4; i++) {
            accz[i] = pack2(bz, 0.f);
            accr[i] = pack2(br, 0.f);
            accp[i] = pack2(b2, 0.f);
        }
        const float4* st4 = (const float4*)stage;

#pragma unroll 1
        for (int q = 0; q < 8; q++) {
            int r = q * 32 + lane;
            float4 z0 = sZ0[r], z1 = sZ1[r], z2 = sZ2[r], z3 = sZ3[r];
            float4 w0 = sR0[r], w1 = sR1[r], w2 = sR2[r], w3 = sR3[r];
            float4 pq0 = sP0[r], pq1 = sP1[r];
#pragma unroll
            for (int i = 0; i < 4; i++) {
                float4 vx = st4[i * 32 +  0 + q];
                float4 va = st4[i * 32 +  8 + q];
                float4 vh = st4[i * 32 + 16 + q];
                float4 vr = st4[i * 32 + 24 + q];
                fma2(accz[i], z0.x, z0.y, vx.x, vx.y); fma2(accz[i], z0.z, z0.w, vx.z, vx.w);
                fma2(accz[i], z1.x, z1.y, va.x, va.y); fma2(accz[i], z1.z, z1.w, va.z, va.w);
                fma2(accz[i], z2.x, z2.y, vh.x, vh.y); fma2(accz[i], z2.z, z2.w, vh.z, vh.w);
                fma2(accz[i], z3.x, z3.y, vr.x, vr.y); fma2(accz[i], z3.z, z3.w, vr.z, vr.w);
                fma2(accr[i], w0.x, w0.y, vx.x, vx.y); fma2(accr[i], w0.z, w0.w, vx.z, vx.w);
                fma2(accr[i], w1.x, w1.y, va.x, va.y); fma2(accr[i], w1.z, w1.w, va.z, va.w);
                fma2(accr[i], w2.x, w2.y, vh.x, vh.y); fma2(accr[i], w2.z, w2.w, vh.z, vh.w);
                fma2(accr[i], w3.x, w3.y, vr.x, vr.y); fma2(accr[i], w3.z, w3.w, vr.z, vr.w);
                fma2(accp[i], pq0.x, pq0.y, vx.x, vx.y); fma2(accp[i], pq0.z, pq0.w, vx.z, vx.w);
                fma2(accp[i], pq1.x, pq1.y, va.x, va.y); fma2(accp[i], pq1.z, pq1.w, va.z, va.w);
            }
        }

#pragma unroll
        for (int i = 0; i < 4; i++) {
            int node = nb + i;
            if (node >= NN) break;
            float2 az = unpack2(accz[i]);
            float2 ar = unpack2(accr[i]);
            float2 ap = unpack2(accp[i]);
            float z = 1.0f / (1.0f + __expf(-(az.x + az.y)));
            float r = 1.0f / (1.0f + __expf(-(ar.x + ar.y)));
            int base = node * CC + lane;
            g_z[base] = z;
            g_hr[base] = hv[i] * r;
            g_px2[base] = ap.x + ap.y;
        }
        __syncwarp();
    }
}

// ---------------- k_final: PURE compute: h_tilde + h_new + head (8 nodes/warp)
__global__ void __launch_bounds__(256) k_final(
        const float* __restrict__ h,
        const float* __restrict__ Wh,
        const float* __restrict__ Wl, const float* __restrict__ bl,
        float* __restrict__ out) {
    extern __shared__ float4 dynq[];
    float4* sQ0 = dynq;          // Wh[2,0] k-quads
    float4* sQ1 = dynq + 256;    // Wh[2,1] k-quads
    __shared__ __align__(16) float sIn[8 * 8 * 2 * 32];
    __shared__ float sWl[32];

    int tid = threadIdx.x;
    for (int i = tid; i < 256; i += blockDim.x) {
        int q = i >> 5, c = i & 31;
        int o = q * 128 + c;
        sQ0[i] = make_float4(Wh[4096 + o], Wh[4096 + o + 32], Wh[4096 + o + 64], Wh[4096 + o + 96]);
        sQ1[i] = make_float4(Wh[5120 + o], Wh[5120 + o + 32], Wh[5120 + o + 64], Wh[5120 + o + 96]);
    }
    if (tid < 32) sWl[tid] = Wl[tid];
    __syncthreads();

    int lane = tid & 31;
    int warp = tid >> 5;
    float blv = bl[0];

    int gw = blockIdx.x * 8 + warp;
    int stride = gridDim.x * 8 * 8;
    float* stage = &sIn[warp * 512];

    for (int nb = gw * 8; nb < NN; nb += stride) {
        float px2r[8];
#pragma unroll
        for (int i = 0; i < 8; i++) {
            int node = nb + i;
            float hrv = 0.f, ahr = 0.f, px = 0.f;
            if (node < NN) {
                int base = node * CC + lane;
                hrv = g_hr[base];
                px = g_px2[base];
                ahr = g_aggx[base];   // agg(hr), written by k_gather_hr
            }
            px2r[i] = px;
            stage[i * 64 +  0 + lane] = hrv;
            stage[i * 64 + 32 + lane] = ahr;
        }
        __syncwarp();

        unsigned long long acc[8];
#pragma unroll
        for (int i = 0; i < 8; i++) acc[i] = pack2(px2r[i], 0.f);
        const float4* st4 = (const float4*)stage;

#pragma unroll 1
        for (int q = 0; q < 8; q++) {
            int r = q * 32 + lane;
            float4 w0 = sQ0[r];
            float4 w1 = sQ1[r];
#pragma unroll
            for (int i = 0; i < 8; i++) {
                float4 vh = st4[i * 16 + 0 + q];
                float4 vr = st4[i * 16 + 8 + q];
                fma2(acc[i], w0.x, w0.y, vh.x, vh.y); fma2(acc[i], w0.z, w0.w, vh.z, vh.w);
                fma2(acc[i], w1.x, w1.y, vr.x, vr.y); fma2(acc[i], w1.z, w1.w, vr.z, vr.w);
            }
        }

#pragma unroll
        for (int i = 0; i < 8; i++) {
            int node = nb + i;
            if (node >= NN) break;
            float2 a2 = unpack2(acc[i]);
            float ht = tanhf(a2.x + a2.y);
            int base = node * CC + lane;
            float zv = g_z[base];
            float hvv = h[base];
            float hn = zv * hvv + (1.0f - zv) * ht;

            out[NN + base] = hn;

            float rl = fmaxf(hn, 0.0f) * sWl[lane];
#pragma unroll
            for (int off = 16; off > 0; off >>= 1)
                rl += __shfl_xor_sync(0xffffffffu, rl, off);
            if (lane == 0) {
                float s = rl + blv;
                out[node] = log1pf(__expf(-fabsf(s))) + fmaxf(s, 0.0f);
            }
        }
        __syncwarp();
    }
}

// ---------------- launch ------------------------------------------------------
extern "C" void kernel_launch(void* const* d_in, const int* in_sizes, int n_in,
                              void* d_out, int out_size) {
    const float* x  = (const float*)d_in[0];
    const int*   ei = (const int*)d_in[1];
    const float* w  = (const float*)d_in[2];
    const float* h  = (const float*)d_in[3];
    const float* Wx = (const float*)d_in[4];
    const float* bx = (const float*)d_in[5];
    const float* Wh = (const float*)d_in[6];
    const float* bh = (const float*)d_in[7];
    const float* Wl = (const float*)d_in[8];
    const float* bl = (const float*)d_in[9];
    float* out = (float*)d_out;

    (void)in_sizes; (void)n_in; (void)out_size;

    cudaFuncSetAttribute(k_gates, cudaFuncAttributeMaxDynamicSharedMemorySize, 40960);
    cudaFuncSetAttribute(k_final, cudaFuncAttributeMaxDynamicSharedMemorySize, 8192);
    cudaFuncSetAttribute(k_gates, cudaFuncAttributePreferredSharedMemoryCarveout, 100);

    void* p_deg = nullptr; cudaGetSymbolAddress(&p_deg, g_deg);
    void* p_zb  = nullptr; cudaGetSymbolAddress(&p_zb, g_zbuf);
    cudaMemsetAsync(p_deg, 0, NN * sizeof(float));
    cudaMemsetAsync(p_zb, 0, (NN + 512) * sizeof(int));

    k_deg_hist<<<(EE / 4 + 255) / 256, 256>>>(ei, w);
    k_scan<<<NB, SCAN_T>>>();
    k_place<<<(EE / 4 + 255) / 256, 256>>>(ei, w);
    k_gather_xh<<<(NN + 7) / 8, 256>>>(x, h);     // warp per node, no smem
    k_gates<<<592, 256, 40960>>>(x, h, Wx, bx, Wh, bh);
    k_gather_hr<<<(NN + 7) / 8, 256>>>();
    k_final<<<592, 256, 8192>>>(h, Wh, Wl, bl, out);
}

// round 10
// speedup vs baseline: 1.4652x; 1.4652x over previous
#include <cuda_runtime.h>
#include <math.h>

#define NN 100000
#define EE 1600000
#define CC 32
#define SCAN_T 512
#define NB ((NN + SCAN_T - 1) / SCAN_T)   /* 196 */

// ---------------- scratch (static device globals; no allocation) -------------
// one zeroed region: [deg: NN floats][cnt: NN ints][scan state: 512 ints]
__device__ __align__(16) int g_zero_region[2 * NN + 512];
__device__ int   g_row[NN + 1];
__device__ int   g_cur[NN];
__device__ int2  g_csr[EE];          // (src, coef bits), grouped by dst
__device__ float g_aggx[NN * CC];    // phase1: agg(x); reused in phase2 as agg(hr)
__device__ float g_aggh[NN * CC];    // agg(h)
__device__ float g_px2[NN * CC];     // gate-2 x-side preactivation (incl. bias)
__device__ float g_z[NN * CC];
__device__ float g_hr[NN * CC];

#define G_DEG   ((float*)g_zero_region)
#define G_CNT   (g_zero_region + NN)
#define G_STATE ((unsigned long long*)(g_zero_region + 2 * NN))

// ---------------- f32x2 packed-FMA helpers -----------------------------------
__device__ __forceinline__ unsigned long long pack2(float a, float b) {
    unsigned long long v;
    asm("mov.b64 %0, {%1, %2};" : "=l"(v) : "f"(a), "f"(b));
    return v;
}
__device__ __forceinline__ float2 unpack2(unsigned long long v) {
    float2 r;
    asm("mov.b64 {%0, %1}, %2;" : "=f"(r.x), "=f"(r.y) : "l"(v));
    return r;
}
__device__ __forceinline__ void fma2(unsigned long long& acc, float w0, float w1,
                                     float s0, float s1) {
    unsigned long long wv = pack2(w0, w1);
    unsigned long long sv = pack2(s0, s1);
    asm("fma.rn.f32x2 %0, %1, %2, %3;" : "=l"(acc) : "l"(wv), "l"(sv), "l"(acc));
}

// ---------------- k_deg_hist: 4 edges per thread ------------------------------
__global__ void k_deg_hist(const int* __restrict__ ei, const float* __restrict__ w) {
    int t = blockIdx.x * blockDim.x + threadIdx.x;
    if (t >= EE / 4) return;
    int4 s = ((const int4*)ei)[t];
    int4 d = ((const int4*)(ei + EE))[t];
    float4 wv = ((const float4*)w)[t];
    atomicAdd(&G_DEG[s.x], wv.x);
    atomicAdd(&G_DEG[s.y], wv.y);
    atomicAdd(&G_DEG[s.z], wv.z);
    atomicAdd(&G_DEG[s.w], wv.w);
    atomicAdd(&G_CNT[d.x], 1);
    atomicAdd(&G_CNT[d.y], 1);
    atomicAdd(&G_CNT[d.z], 1);
    atomicAdd(&G_CNT[d.w], 1);
}

// ---------------- k_scan: single-pass exclusive scan, warp-parallel lookback --
__global__ void k_scan() {
    __shared__ int s[SCAN_T];
    __shared__ int sPrefix;
    unsigned long long* state = G_STATE;
    int t = threadIdx.x;
    int b = blockIdx.x;
    int i = b * SCAN_T + t;
    int v = (i < NN) ? G_CNT[i] : 0;
    s[t] = v;
    __syncthreads();
    for (int off = 1; off < SCAN_T; off <<= 1) {
        int a = (t >= off) ? s[t - off] : 0;
        __syncthreads();
        s[t] += a;
        __syncthreads();
    }
    int total = s[SCAN_T - 1];

    if (b == 0) {
        if (t == 0) { atomicExch(&state[0], (2ULL << 32) | (unsigned)total); sPrefix = 0; }
    } else if (t < 32) {
        if (t == 0) atomicExch(&state[b], (1ULL << 32) | (unsigned)total);
        int prefix = 0;
        int j = b - 1 - t;
        for (;;) {
            unsigned flag = 0; int val = 0;
            if (j >= 0) {
                unsigned long long sj;
                do { sj = atomicOr(&state[j], 0ULL); flag = (unsigned)(sj >> 32); }
                while (flag == 0u);
                val = (int)(unsigned)sj;
            }
            unsigned incmask = __ballot_sync(0xffffffffu, (j >= 0) && flag == 2u);
            if (incmask) {
                int k = __ffs(incmask) - 1;
                if (t > k) val = 0;
            }
#pragma unroll
            for (int off = 16; off > 0; off >>= 1)
                val += __shfl_xor_sync(0xffffffffu, val, off);
            prefix += val;
            if (incmask) break;
            j -= 32;
        }
        if (t == 0) {
            atomicExch(&state[b], (2ULL << 32) | (unsigned)(prefix + total));
            sPrefix = prefix;
        }
    }
    __syncthreads();
    int pre = (b == 0) ? 0 : sPrefix;
    if (i < NN) {
        int rs = pre + s[t] - v;
        g_row[i] = rs;
        g_cur[i] = rs;
    }
    if (b == 0 && t == 0) g_row[NN] = EE;
}

// ---------------- k_place: 4 edges per thread ---------------------------------
__global__ void k_place(const int* __restrict__ ei, const float* __restrict__ w) {
    int t = blockIdx.x * blockDim.x + threadIdx.x;
    if (t >= EE / 4) return;
    int4 s = ((const int4*)ei)[t];
    int4 d = ((const int4*)(ei + EE))[t];
    float4 wv = ((const float4*)w)[t];
    float ds0 = G_DEG[s.x], ds1 = G_DEG[s.y], ds2 = G_DEG[s.z], ds3 = G_DEG[s.w];
    float dd0 = G_DEG[d.x], dd1 = G_DEG[d.y], dd2 = G_DEG[d.z], dd3 = G_DEG[d.w];
    float c0 = -((ds0 > 0.f ? rsqrtf(ds0) : 0.f) * wv.x * (dd0 > 0.f ? rsqrtf(dd0) : 0.f));
    float c1 = -((ds1 > 0.f ? rsqrtf(ds1) : 0.f) * wv.y * (dd1 > 0.f ? rsqrtf(dd1) : 0.f));
    float c2 = -((ds2 > 0.f ? rsqrtf(ds2) : 0.f) * wv.z * (dd2 > 0.f ? rsqrtf(dd2) : 0.f));
    float c3 = -((ds3 > 0.f ? rsqrtf(ds3) : 0.f) * wv.w * (dd3 > 0.f ? rsqrtf(dd3) : 0.f));
    int p0 = atomicAdd(&g_cur[d.x], 1);
    int p1 = atomicAdd(&g_cur[d.y], 1);
    int p2 = atomicAdd(&g_cur[d.z], 1);
    int p3 = atomicAdd(&g_cur[d.w], 1);
    g_csr[p0] = make_int2(s.x, __float_as_int(c0));
    g_csr[p1] = make_int2(s.y, __float_as_int(c1));
    g_csr[p2] = make_int2(s.z, __float_as_int(c2));
    g_csr[p3] = make_int2(s.w, __float_as_int(c3));
}

// ---------------- gathers (unroll 8 for MLP) -----------------------------------
__device__ __forceinline__ void gather2(int node, int lane,
                                        const float* __restrict__ a,
                                        const float* __restrict__ b,
                                        float& ra, float& rb) {
    int beg = g_row[node], end = g_row[node + 1];
    float sa = 0.0f, sb = 0.0f;
    int e = beg;
    for (; e + 8 <= end; e += 8) {
        int2 t0 = g_csr[e],     t1 = g_csr[e + 1], t2 = g_csr[e + 2], t3 = g_csr[e + 3];
        int2 t4 = g_csr[e + 4], t5 = g_csr[e + 5], t6 = g_csr[e + 6], t7 = g_csr[e + 7];
        float a0 = a[t0.x * CC + lane], a1 = a[t1.x * CC + lane];
        float a2 = a[t2.x * CC + lane], a3 = a[t3.x * CC + lane];
        float a4 = a[t4.x * CC + lane], a5 = a[t5.x * CC + lane];
        float a6 = a[t6.x * CC + lane], a7 = a[t7.x * CC + lane];
        float b0 = b[t0.x * CC + lane], b1 = b[t1.x * CC + lane];
        float b2 = b[t2.x * CC + lane], b3 = b[t3.x * CC + lane];
        float b4 = b[t4.x * CC + lane], b5 = b[t5.x * CC + lane];
        float b6 = b[t6.x * CC + lane], b7 = b[t7.x * CC + lane];
        sa += __int_as_float(t0.y) * a0 + __int_as_float(t1.y) * a1
            + __int_as_float(t2.y) * a2 + __int_as_float(t3.y) * a3
            + __int_as_float(t4.y) * a4 + __int_as_float(t5.y) * a5
            + __int_as_float(t6.y) * a6 + __int_as_float(t7.y) * a7;
        sb += __int_as_float(t0.y) * b0 + __int_as_float(t1.y) * b1
            + __int_as_float(t2.y) * b2 + __int_as_float(t3.y) * b3
            + __int_as_float(t4.y) * b4 + __int_as_float(t5.y) * b5
            + __int_as_float(t6.y) * b6 + __int_as_float(t7.y) * b7;
    }
    for (; e < end; e++) {
        int2 t = g_csr[e];
        float c = __int_as_float(t.y);
        sa += c * a[t.x * CC + lane];
        sb += c * b[t.x * CC + lane];
    }
    ra = sa; rb = sb;
}

__device__ __forceinline__ void gather1(int node, int lane,
                                        const float* __restrict__ a, float& ra) {
    int beg = g_row[node], end = g_row[node + 1];
    float sa = 0.0f;
    int e = beg;
    for (; e + 8 <= end; e += 8) {
        int2 t0 = g_csr[e],     t1 = g_csr[e + 1], t2 = g_csr[e + 2], t3 = g_csr[e + 3];
        int2 t4 = g_csr[e + 4], t5 = g_csr[e + 5], t6 = g_csr[e + 6], t7 = g_csr[e + 7];
        float a0 = a[t0.x * CC + lane], a1 = a[t1.x * CC + lane];
        float a2 = a[t2.x * CC + lane], a3 = a[t3.x * CC + lane];
        float a4 = a[t4.x * CC + lane], a5 = a[t5.x * CC + lane];
        float a6 = a[t6.x * CC + lane], a7 = a[t7.x * CC + lane];
        sa += __int_as_float(t0.y) * a0 + __int_as_float(t1.y) * a1
            + __int_as_float(t2.y) * a2 + __int_as_float(t3.y) * a3
            + __int_as_float(t4.y) * a4 + __int_as_float(t5.y) * a5
            + __int_as_float(t6.y) * a6 + __int_as_float(t7.y) * a7;
    }
    for (; e < end; e++) {
        int2 t = g_csr[e];
        sa += __int_as_float(t.y) * a[t.x * CC + lane];
    }
    ra = sa;
}

// ---------------- k_gather_xh: warp-per-node, zero smem, max occupancy --------
__global__ void __launch_bounds__(256) k_gather_xh(
        const float* __restrict__ x, const float* __restrict__ h) {
    int lane = threadIdx.x & 31;
    int node = (blockIdx.x * blockDim.x + threadIdx.x) >> 5;
    if (node >= NN) return;
    float ax, ah;
    gather2(node, lane, x, h, ax, ah);
    int base = node * CC + lane;
    g_aggx[base] = ax;
    g_aggh[base] = ah;
}

// ---------------- k_gather_hr: warp-per-node gather of hr ---------------------
__global__ void __launch_bounds__(256) k_gather_hr() {
    int lane = threadIdx.x & 31;
    int node = (blockIdx.x * blockDim.x + threadIdx.x) >> 5;
    if (node >= NN) return;
    float ahr;
    gather1(node, lane, g_hr, ahr);
    g_aggx[node * CC + lane] = ahr;   // aggx dead after k_gates
}

// ---------------- k_gates: PURE compute, vectorized stage fill ----------------
__global__ void __launch_bounds__(256) k_gates(
        const float* __restrict__ x, const float* __restrict__ h,
        const float* __restrict__ Wx, const float* __restrict__ bx,
        const float* __restrict__ Wh, const float* __restrict__ bh) {
    extern __shared__ float4 dynw[];
    float4* sZ0 = dynw;            // z: Wx[0,0] k-quads
    float4* sZ1 = dynw + 256;      // z: Wx[0,1]
    float4* sZ2 = dynw + 512;      // z: Wh[0,0]
    float4* sZ3 = dynw + 768;      // z: Wh[0,1]
    float4* sR0 = dynw + 1024;     // r: Wx[1,0]
    float4* sR1 = dynw + 1280;     // r: Wx[1,1]
    float4* sR2 = dynw + 1536;     // r: Wh[1,0]
    float4* sR3 = dynw + 1792;     // r: Wh[1,1]
    float4* sP0 = dynw + 2048;     // px2: Wx[2,0]
    float4* sP1 = dynw + 2304;     // px2: Wx[2,1]
    __shared__ __align__(16) float sIn[8 * 4 * 4 * 32];  // 16KB

    int tid = threadIdx.x;
    for (int i = tid; i < 256; i += blockDim.x) {
        int q = i >> 5, c = i & 31;
        int o = q * 128 + c;
        sZ0[i] = make_float4(Wx[o],        Wx[o + 32],        Wx[o + 64],        Wx[o + 96]);
        sZ1[i] = make_float4(Wx[1024 + o], Wx[1024 + o + 32], Wx[1024 + o + 64], Wx[1024 + o + 96]);
        sZ2[i] = make_float4(Wh[o],        Wh[o + 32],        Wh[o + 64],        Wh[o + 96]);
        sZ3[i] = make_float4(Wh[1024 + o], Wh[1024 + o + 32], Wh[1024 + o + 64], Wh[1024 + o + 96]);
        sR0[i] = make_float4(Wx[2048 + o], Wx[2048 + o + 32], Wx[2048 + o + 64], Wx[2048 + o + 96]);
        sR1[i] = make_float4(Wx[3072 + o], Wx[3072 + o + 32], Wx[3072 + o + 64], Wx[3072 + o + 96]);
        sR2[i] = make_float4(Wh[2048 + o], Wh[2048 + o + 32], Wh[2048 + o + 64], Wh[2048 + o + 96]);
        sR3[i] = make_float4(Wh[3072 + o], Wh[3072 + o + 32], Wh[3072 + o + 64], Wh[3072 + o + 96]);
        sP0[i] = make_float4(Wx[4096 + o], Wx[4096 + o + 32], Wx[4096 + o + 64], Wx[4096 + o + 96]);
        sP1[i] = make_float4(Wx[5120 + o], Wx[5120 + o + 32], Wx[5120 + o + 64], Wx[5120 + o + 96]);
    }
    __syncthreads();

    int lane = tid & 31;
    int warp = tid >> 5;
    float bz = bx[lane] + bh[lane];
    float br = bx[32 + lane] + bh[32 + lane];
    float b2 = bx[64 + lane] + bh[64 + lane];

    int sub  = lane >> 3;        // node index within 4-group for fill
    int qd   = (lane & 7);       // float4 index within row

    int gw = blockIdx.x * 8 + warp;
    int stride = gridDim.x * 8 * 4;
    float* stage = &sIn[warp * 512];
    float4* st4w = (float4*)stage;

    // NN % 4 == 0 so every group is full
    for (int nb = gw * 4; nb < NN; nb += stride) {
        // ---- vectorized stage fill: 4 LDG.128 + 4 STS.128 per group ----
        {
            long ofs = (long)(nb + sub) * CC + qd * 4;
            float4 vx = *(const float4*)(x + ofs);
            float4 va = *(const float4*)(g_aggx + ofs);
            float4 vh = *(const float4*)(h + ofs);
            float4 vg = *(const float4*)(g_aggh + ofs);
            st4w[sub * 32 +  0 + qd] = vx;
            st4w[sub * 32 +  8 + qd] = va;
            st4w[sub * 32 + 16 + qd] = vh;
            st4w[sub * 32 + 24 + qd] = vg;
        }
        __syncwarp();

        unsigned long long accz[4], accr[4], accp[4];
#pragma unroll
        for (int i = 0; i < 4; i++) {
            accz[i] = pack2(bz, 0.f);
            accr[i] = pack2(br, 0.f);
            accp[i] = pack2(b2, 0.f);
        }
        const float4* st4 = (const float4*)stage;

#pragma unroll 1
        for (int q = 0; q < 8; q++) {
            int r = q * 32 + lane;
            float4 z0 = sZ0[r], z1 = sZ1[r], z2 = sZ2[r], z3 = sZ3[r];
            float4 w0 = sR0[r], w1 = sR1[r], w2 = sR2[r], w3 = sR3[r];
            float4 pq0 = sP0[r], pq1 = sP1[r];
#pragma unroll
            for (int i = 0; i < 4; i++) {
                float4 vx = st4[i * 32 +  0 + q];
                float4 va = st4[i * 32 +  8 + q];
                float4 vh = st4[i * 32 + 16 + q];
                float4 vr = st4[i * 32 + 24 + q];
                fma2(accz[i], z0.x, z0.y, vx.x, vx.y); fma2(accz[i], z0.z, z0.w, vx.z, vx.w);
                fma2(accz[i], z1.x, z1.y, va.x, va.y); fma2(accz[i], z1.z, z1.w, va.z, va.w);
                fma2(accz[i], z2.x, z2.y, vh.x, vh.y); fma2(accz[i], z2.z, z2.w, vh.z, vh.w);
                fma2(accz[i], z3.x, z3.y, vr.x, vr.y); fma2(accz[i], z3.z, z3.w, vr.z, vr.w);
                fma2(accr[i], w0.x, w0.y, vx.x, vx.y); fma2(accr[i], w0.z, w0.w, vx.z, vx.w);
                fma2(accr[i], w1.x, w1.y, va.x, va.y); fma2(accr[i], w1.z, w1.w, va.z, va.w);
                fma2(accr[i], w2.x, w2.y, vh.x, vh.y); fma2(accr[i], w2.z, w2.w, vh.z, vh.w);
                fma2(accr[i], w3.x, w3.y, vr.x, vr.y); fma2(accr[i], w3.z, w3.w, vr.z, vr.w);
                fma2(accp[i], pq0.x, pq0.y, vx.x, vx.y); fma2(accp[i], pq0.z, pq0.w, vx.z, vx.w);
                fma2(accp[i], pq1.x, pq1.y, va.x, va.y); fma2(accp[i], pq1.z, pq1.w, va.z, va.w);
            }
        }

#pragma unroll
        for (int i = 0; i < 4; i++) {
            int node = nb + i;
            float2 az = unpack2(accz[i]);
            float2 ar = unpack2(accr[i]);
            float2 ap = unpack2(accp[i]);
            float z = 1.0f / (1.0f + __expf(-(az.x + az.y)));
            float r = 1.0f / (1.0f + __expf(-(ar.x + ar.y)));
            int base = node * CC + lane;
            float hvv = stage[i * 128 + 64 + lane];
            g_z[base] = z;
            g_hr[base] = hvv * r;
            g_px2[base] = ap.x + ap.y;
        }
        __syncwarp();
    }
}

// ---------------- k_final: PURE compute, vectorized fill (8 nodes/warp) -------
__global__ void __launch_bounds__(256) k_final(
        const float* __restrict__ h,
        const float* __restrict__ Wh,
        const float* __restrict__ Wl, const float* __restrict__ bl,
        float* __restrict__ out) {
    extern __shared__ float4 dynq[];
    float4* sQ0 = dynq;          // Wh[2,0] k-quads
    float4* sQ1 = dynq + 256;    // Wh[2,1] k-quads
    __shared__ __align__(16) float sIn[8 * 8 * 2 * 32];
    __shared__ float sWl[32];

    int tid = threadIdx.x;
    for (int i = tid; i < 256; i += blockDim.x) {
        int q = i >> 5, c = i & 31;
        int o = q * 128 + c;
        sQ0[i] = make_float4(Wh[4096 + o], Wh[4096 + o + 32], Wh[4096 + o + 64], Wh[4096 + o + 96]);
        sQ1[i] = make_float4(Wh[5120 + o], Wh[5120 + o + 32], Wh[5120 + o + 64], Wh[5120 + o + 96]);
    }
    if (tid < 32) sWl[tid] = Wl[tid];
    __syncthreads();

    int lane = tid & 31;
    int warp = tid >> 5;
    float blv = bl[0];
    int sub = lane >> 3;
    int qd  = lane & 7;

    int gw = blockIdx.x * 8 + warp;
    int stride = gridDim.x * 8 * 8;
    float* stage = &sIn[warp * 512];
    float4* st4w = (float4*)stage;

    // NN % 8 == 0 so every group is full
    for (int nb = gw * 8; nb < NN; nb += stride) {
        float px2r[8];
        // ---- vectorized fill: 4 LDG.128 + 4 STS.128 (two halves) ----
#pragma unroll
        for (int half = 0; half < 2; half++) {
            int node = nb + half * 4 + sub;
            long ofs = (long)node * CC + qd * 4;
            float4 vh = *(const float4*)(g_hr + ofs);
            float4 vr = *(const float4*)(g_aggx + ofs);   // agg(hr)
            st4w[(half * 4 + sub) * 16 + 0 + qd] = vh;
            st4w[(half * 4 + sub) * 16 + 8 + qd] = vr;
        }
#pragma unroll
        for (int i = 0; i < 8; i++)
            px2r[i] = g_px2[(nb + i) * CC + lane];
        __syncwarp();

        unsigned long long acc[8];
#pragma unroll
        for (int i = 0; i < 8; i++) acc[i] = pack2(px2r[i], 0.f);
        const float4* st4 = (const float4*)stage;

#pragma unroll 1
        for (int q = 0; q < 8; q++) {
            int r = q * 32 + lane;
            float4 w0 = sQ0[r];
            float4 w1 = sQ1[r];
#pragma unroll
            for (int i = 0; i < 8; i++) {
                float4 vh = st4[i * 16 + 0 + q];
                float4 vr = st4[i * 16 + 8 + q];
                fma2(acc[i], w0.x, w0.y, vh.x, vh.y); fma2(acc[i], w0.z, w0.w, vh.z, vh.w);
                fma2(acc[i], w1.x, w1.y, vr.x, vr.y); fma2(acc[i], w1.z, w1.w, vr.z, vr.w);
            }
        }

#pragma unroll
        for (int i = 0; i < 8; i++) {
            int node = nb + i;
            float2 a2 = unpack2(acc[i]);
            float ht = tanhf(a2.x + a2.y);
            int base = node * CC + lane;
            float zv = g_z[base];
            float hvv = h[base];
            float hn = zv * hvv + (1.0f - zv) * ht;

            out[NN + base] = hn;

            float rl = fmaxf(hn, 0.0f) * sWl[lane];
#pragma unroll
            for (int off = 16; off > 0; off >>= 1)
                rl += __shfl_xor_sync(0xffffffffu, rl, off);
            if (lane == 0) {
                float s = rl + blv;
                out[node] = log1pf(__expf(-fabsf(s))) + fmaxf(s, 0.0f);
            }
        }
        __syncwarp();
    }
}

// ---------------- launch ------------------------------------------------------
extern "C" void kernel_launch(void* const* d_in, const int* in_sizes, int n_in,
                              void* d_out, int out_size) {
    const float* x  = (const float*)d_in[0];
    const int*   ei = (const int*)d_in[1];
    const float* w  = (const float*)d_in[2];
    const float* h  = (const float*)d_in[3];
    const float* Wx = (const float*)d_in[4];
    const float* bx = (const float*)d_in[5];
    const float* Wh = (const float*)d_in[6];
    const float* bh = (const float*)d_in[7];
    const float* Wl = (const float*)d_in[8];
    const float* bl = (const float*)d_in[9];
    float* out = (float*)d_out;

    (void)in_sizes; (void)n_in; (void)out_size;

    cudaFuncSetAttribute(k_gates, cudaFuncAttributeMaxDynamicSharedMemorySize, 40960);
    cudaFuncSetAttribute(k_final, cudaFuncAttributeMaxDynamicSharedMemorySize, 8192);

    void* p_zr = nullptr; cudaGetSymbolAddress(&p_zr, g_zero_region);
    cudaMemsetAsync(p_zr, 0, (2 * NN + 512) * sizeof(int));   // launch 1

    k_deg_hist<<<(EE / 4 + 255) / 256, 256>>>(ei, w);         // 2
    k_scan<<<NB, SCAN_T>>>();                                 // 3
    k_place<<<(EE / 4 + 255) / 256, 256>>>(ei, w);            // 4
    k_gather_xh<<<(NN + 7) / 8, 256>>>(x, h);                 // 5
    k_gates<<<592, 256, 40960>>>(x, h, Wx, bx, Wh, bh);       // 6 <- profiled
    k_gather_hr<<<(NN + 7) / 8, 256>>>();                     // 7
    k_final<<<592, 256, 8192>>>(h, Wh, Wl, bl, out);          // 8
}